// round 9
// baseline (speedup 1.0000x reference)
#include <cuda_runtime.h>
#include <cuda_bf16.h>
#include <cstdint>
#include <math.h>

#define Bb 8
#define Nn 256
#define DEe 768
#define DH 192
#define Ll 2
#define DCc 192
#define G3 576
#define HCW 576
#define CSZ 8           // cluster size (CTAs per batch)
#define DSL 24          // DH / CSZ columns per CTA

// ---- smem float offsets (scan kernel) ----
#define OFF_WC   0                    // 48*72*4 = 13824
#define OFF_WP   13824                // 13824
#define OFF_WR0  27648                // 48*24*4 = 4608
#define OFF_WR1  32256                // 4608
#define OFF_V0   36864                // 256*24 = 6144
#define OFF_V1   43008                // 6144
#define OFF_KSC  49152                // 256
#define OFF_A0   49408                // 256
#define OFF_A1   49664                // 256
#define OFF_M    49920                // 192 (16B aligned)
#define OFF_H    50112                // 192 (16B aligned)
#define OFF_WK   50304                // 192
#define OFF_GC   50496                // 72
#define OFF_GP   50568                // 72
#define OFF_GI   50640                // 72
#define OFF_GH   50712                // 72
#define OFF_X    50784                // 24
#define OFF_MP   50808                // 8*24 = 192 (also M staging; 16B aligned)
#define OFF_BC   51000                // 72
#define OFF_BP   51072                // 72
#define OFF_RED2 51152                // 8
#define OFF_ADJ  51160                // 256 prefetched adj row
#define OFF_SM2  51416                // 256 prefetched smask row
#define OFF_MBAR 51672                // 2 x u64 mbarriers (8B aligned)
#define OFF_HS   51676                // 24-float H staging (16B aligned)
#define SCAN_SMEM_FLOATS 51700
#define SCAN_SMEM_BYTES (SCAN_SMEM_FLOATS * 4)

__device__ float g_Hcat[Bb * Nn * HCW];
__device__ float g_GI[Bb * Nn * G3];
__device__ float g_GH[Bb * Nn * G3];
__device__ float g_h1[Bb * Nn * DH];
__device__ float g_h2[Bb * Nn * DH];

__device__ __forceinline__ float warpRedSum(float v) {
#pragma unroll
    for (int o = 16; o > 0; o >>= 1) v += __shfl_xor_sync(0xffffffffu, v, o);
    return v;
}
__device__ __forceinline__ void cluster_sync_() {
    asm volatile("barrier.cluster.arrive.aligned;" ::: "memory");
    asm volatile("barrier.cluster.wait.aligned;" ::: "memory");
}
__device__ __forceinline__ uint32_t smem_u32(const void* p) {
    uint32_t a;
    asm("{ .reg .u64 t; cvta.to.shared.u64 t, %1; cvt.u32.u64 %0, t; }" : "=r"(a) : "l"(p));
    return a;
}
// Bulk-copy the 96B staged slice to slot (OFF + c*96B) in all 8 cluster CTAs,
// accounting 96B on each remote mbarrier. ONE thread calls this.
__device__ __forceinline__ void bulk_bcast_slice(uint32_t src, uint32_t dst_base,
                                                 uint32_t mbar_loc) {
#pragma unroll
    for (int r = 0; r < CSZ; ++r) {
        uint32_t rd, rb;
        asm("mapa.shared::cluster.u32 %0, %1, %2;" : "=r"(rd) : "r"(dst_base), "r"(r));
        asm("mapa.shared::cluster.u32 %0, %1, %2;" : "=r"(rb) : "r"(mbar_loc), "r"(r));
        asm volatile(
            "cp.async.bulk.shared::cluster.shared::cta.mbarrier::complete_tx::bytes "
            "[%0], [%1], 96, [%2];"
            :: "r"(rd), "r"(src), "r"(rb) : "memory");
    }
}
__device__ __forceinline__ void mbar_wait_parity(uint32_t mbar, uint32_t parity) {
    uint32_t done;
    asm volatile(
        "{\n\t.reg .pred p;\n\t"
        "mbarrier.try_wait.parity.acquire.cta.shared::cta.b64 p, [%1], %2;\n\t"
        "selp.b32 %0, 1, 0, p;\n\t}"
        : "=r"(done) : "r"(mbar), "r"(parity) : "memory");
    while (!done) {
        asm volatile(
            "{\n\t.reg .pred p;\n\t"
            "mbarrier.try_wait.parity.acquire.cta.shared::cta.b64 p, [%1], %2, 0x989680;\n\t"
            "selp.b32 %0, 1, 0, p;\n\t}"
            : "=r"(done) : "r"(mbar), "r"(parity) : "memory");
    }
}

// ---------------- generic tiled SGEMM (prologue / epilogue) ----------------
template <int TRANSB, int RELU>
__global__ __launch_bounds__(256) void gemm_kernel(
    const float* __restrict__ A, const float* __restrict__ Bm,
    const float* __restrict__ bias, float* __restrict__ C,
    int M, int Nc, int K, int lda, int aoff, int ldc, int coff)
{
    __shared__ float As[16][65];
    __shared__ float Bs[16][65];
    const int tid = threadIdx.x;
    const int bm = blockIdx.y * 64;
    const int bn = blockIdx.x * 64;
    const int tx = tid & 15;
    const int ty = tid >> 4;
    float acc[4][4] = {};

    for (int k0 = 0; k0 < K; k0 += 16) {
        {
            int r = tid >> 2, cs = (tid & 3) * 4;
            float4 v = *reinterpret_cast<const float4*>(
                A + (size_t)(bm + r) * lda + aoff + k0 + cs);
            As[cs + 0][r] = v.x; As[cs + 1][r] = v.y;
            As[cs + 2][r] = v.z; As[cs + 3][r] = v.w;
        }
        if (TRANSB) {
            int n = tid >> 2, ks = (tid & 3) * 4;
            float4 v = *reinterpret_cast<const float4*>(
                Bm + (size_t)(bn + n) * K + k0 + ks);
            Bs[ks + 0][n] = v.x; Bs[ks + 1][n] = v.y;
            Bs[ks + 2][n] = v.z; Bs[ks + 3][n] = v.w;
        } else {
            int r = tid >> 4, cs = (tid & 15) * 4;
            float4 v = *reinterpret_cast<const float4*>(
                Bm + (size_t)(k0 + r) * Nc + bn + cs);
            Bs[r][cs + 0] = v.x; Bs[r][cs + 1] = v.y;
            Bs[r][cs + 2] = v.z; Bs[r][cs + 3] = v.w;
        }
        __syncthreads();
#pragma unroll
        for (int k = 0; k < 16; ++k) {
            float a[4], bv[4];
#pragma unroll
            for (int q = 0; q < 4; ++q) a[q] = As[k][ty * 4 + q];
#pragma unroll
            for (int q = 0; q < 4; ++q) bv[q] = Bs[k][tx * 4 + q];
#pragma unroll
            for (int p = 0; p < 4; ++p)
#pragma unroll
                for (int q = 0; q < 4; ++q)
                    acc[p][q] = fmaf(a[p], bv[q], acc[p][q]);
        }
        __syncthreads();
    }
#pragma unroll
    for (int p = 0; p < 4; ++p) {
        const int m = bm + ty * 4 + p;
#pragma unroll
        for (int q = 0; q < 4; ++q) {
            const int n = bn + tx * 4 + q;
            float v = acc[p][q] + bias[n];
            if (RELU) v = fmaxf(v, 0.f);
            C[(size_t)m * ldc + coff + n] = v;
        }
    }
}

// ---------------- clustered scan: 8 CTAs per batch, smem-resident state ----
__global__ __launch_bounds__(256, 1) void scan2_kernel(
    const float* __restrict__ adj, const float* __restrict__ smask,
    const float* __restrict__ GIc, const float* __restrict__ GHp,
    const float* __restrict__ cwhh,   // (576,192) raw
    const float* __restrict__ pwih,   // (576,192) raw
    const float* __restrict__ cbhh, const float* __restrict__ pbih,
    const float* __restrict__ wr0, const float* __restrict__ wr1, // (192,192) raw
    const float* __restrict__ wk,
    float* __restrict__ Hcat, int layer,
    float* __restrict__ attn_out)
{
    extern __shared__ float sm[];
    const int t = threadIdx.x;
    const int lane = t & 31;
    const int warp = t >> 5;
    uint32_t c;
    asm("mov.u32 %0, %%cluster_ctarank;" : "=r"(c));
    const int b = blockIdx.x / CSZ;

    const uint32_t mbM = smem_u32(sm + OFF_MBAR);
    const uint32_t mbH = mbM + 8;
    const uint32_t stgM = smem_u32(sm + OFF_MP);
    const uint32_t stgH = smem_u32(sm + OFF_HS);
    const uint32_t dstM = smem_u32(sm + OFF_M) + c * 96;
    const uint32_t dstH = smem_u32(sm + OFF_H) + c * 96;

    // ---- prologue: load weight slices into smem ----
    for (int idx = t; idx < 72 * 48; idx += 256) {
        int o = idx / 48, d4 = idx % 48;
        int col = (o / DSL) * DH + c * DSL + (o % DSL);
        float4 vc = *reinterpret_cast<const float4*>(cwhh + (size_t)col * DH + 4 * d4);
        float4 vp = *reinterpret_cast<const float4*>(pwih + (size_t)col * DH + 4 * d4);
        float* dc = sm + OFF_WC + (d4 * 72 + o) * 4;
        float* dp = sm + OFF_WP + (d4 * 72 + o) * 4;
        dc[0] = vc.x; dc[1] = vc.y; dc[2] = vc.z; dc[3] = vc.w;
        dp[0] = vp.x; dp[1] = vp.y; dp[2] = vp.z; dp[3] = vp.w;
    }
    for (int idx = t; idx < DSL * 48; idx += 256) {
        int j = idx / 48, d4 = idx % 48;
        int r0 = c * DSL + j;
        float4 v0 = *reinterpret_cast<const float4*>(wr0 + (size_t)r0 * DH + 4 * d4);
        float4 v1 = *reinterpret_cast<const float4*>(wr1 + (size_t)r0 * DH + 4 * d4);
        float* d0 = sm + OFF_WR0 + (d4 * DSL + j) * 4;
        float* d1 = sm + OFF_WR1 + (d4 * DSL + j) * 4;
        d0[0] = v0.x; d0[1] = v0.y; d0[2] = v0.z; d0[3] = v0.w;
        d1[0] = v1.x; d1[1] = v1.y; d1[2] = v1.z; d1[3] = v1.w;
    }
    if (t < 72) {
        int col = (t / DSL) * DH + c * DSL + (t % DSL);
        sm[OFF_BC + t] = cbhh[col];
        sm[OFF_BP + t] = pbih[col];
    }
    if (t < DH) sm[OFF_WK + t] = wk[t];
    if (t < Nn) {
        sm[OFF_KSC + t] = 0.f;
        sm[OFF_ADJ + t] = 0.f;
        sm[OFF_SM2 + t] = 0.f;
    }
    if (t == 0) {
        asm volatile("mbarrier.init.shared.b64 [%0], 1;" :: "r"(mbM) : "memory");
        asm volatile("mbarrier.init.shared.b64 [%0], 1;" :: "r"(mbH) : "memory");
    }
    __syncthreads();
    cluster_sync_();   // mbarriers + smem visible cluster-wide before any bulk

    const int dB = t % DSL;
    const int gB = t / DSL;
    const float4* sM4 = reinterpret_cast<const float4*>(sm + OFF_M);
    const float4* sH4 = reinterpret_cast<const float4*>(sm + OFF_H);

    for (int i = 0; i < Nn; ++i) {
        const size_t row = (size_t)b * Nn + i;
        const uint32_t par = (uint32_t)(i & 1);

        if (t == 0) {
            asm volatile("mbarrier.arrive.expect_tx.shared.b64 _, [%0], %1;"
                         :: "r"(mbM), "r"(768u) : "memory");
            asm volatile("mbarrier.arrive.expect_tx.shared.b64 _, [%0], %1;"
                         :: "r"(mbH), "r"(768u) : "memory");
        }

        // ---- Phase A: masked softmax (no max-shift; logits bounded) ----
        bool valid = (t < i) && (sm[OFF_ADJ + t] > 0.5f);
        float smv = sm[OFF_SM2 + t];
        float e = valid ? __expf(sm[OFF_KSC + t]) : 0.f;
        float ws = warpRedSum(e);
        if (lane == 0) sm[OFF_RED2 + warp] = ws;
        __syncthreads();
        float tot = sm[OFF_RED2 + 0];
#pragma unroll
        for (int q = 1; q < 8; ++q) tot += sm[OFF_RED2 + q];
        {
            float attn = 0.f;
            if (i > 0) attn = e / tot;
            float a0 = attn * smv;
            sm[OFF_A0 + t] = a0;
            sm[OFF_A1 + t] = attn - a0;
            if (c == 0)
                attn_out[(((size_t)b * Ll + layer) * Nn + i) * Nn + t] = attn;
        }
        __syncthreads();

        // ---- Phase B: partial M over owned columns; threads>=192 prefetch ----
        if (t < 192) {
            float acc = 0.f;
            for (int n = gB; n < i; n += 8) {
                acc = fmaf(sm[OFF_A0 + n], sm[OFF_V0 + n * DSL + dB], acc);
                acc = fmaf(sm[OFF_A1 + n], sm[OFF_V1 + n * DSL + dB], acc);
            }
            sm[OFF_MP + gB * DSL + dB] = acc;
        } else {
            int tp = t - 192;
            for (int u = tp; u < 168; u += 64) {
                if (u < 72) {
                    int col = (u / DSL) * DH + c * DSL + (u % DSL);
                    sm[OFF_GI + u] = GIc[row * G3 + col];
                } else if (u < 144) {
                    int uu = u - 72;
                    int col = (uu / DSL) * DH + c * DSL + (uu % DSL);
                    sm[OFF_GH + uu] = GHp[row * G3 + col];
                } else {
                    int j = u - 144;
                    sm[OFF_X + j] = Hcat[row * HCW + layer * DH + c * DSL + j];
                }
            }
        }
        __syncthreads();
        if (t < DSL) {
            float v = sm[OFF_MP + t];
#pragma unroll
            for (int g = 1; g < 8; ++g) v += sm[OFF_MP + g * DSL + t];
            sm[OFF_MP + t] = v;            // stage own M slice (96B)
        }
        if (warp == 0) {
            __syncwarp();
            if (t == 0) {
                asm volatile("fence.proxy.async.shared::cta;" ::: "memory");
                bulk_bcast_slice(stgM, dstM, mbM);   // ONE 96B bulk per rank
            }
        }
        mbar_wait_parity(mbM, par);   // full M everywhere

        // ---- Phase C: gh_C / gi_P for owned 72+72 outputs; others prefetch ----
        if (t < 144) {
            const int isP = (t >= 72);
            const int o = isP ? t - 72 : t;
            const float* W = sm + (isP ? OFF_WP : OFF_WC);
            float a0 = isP ? sm[OFF_BP + o] : sm[OFF_BC + o];
            float a1 = 0.f, a2 = 0.f, a3 = 0.f;
#pragma unroll 8
            for (int d4 = 0; d4 < 48; ++d4) {
                float4 m4 = sM4[d4];
                const float4 w4 = *reinterpret_cast<const float4*>(W + (d4 * 72 + o) * 4);
                a0 = fmaf(m4.x, w4.x, a0);
                a1 = fmaf(m4.y, w4.y, a1);
                a2 = fmaf(m4.z, w4.z, a2);
                a3 = fmaf(m4.w, w4.w, a3);
            }
            sm[(isP ? OFF_GP : OFF_GC) + o] = (a0 + a1) + (a2 + a3);
        } else if (i + 1 < Nn) {
            // prefetch adj/smask row i+1 for next step's Phase A
            const float4* a4 = reinterpret_cast<const float4*>(
                adj + ((size_t)b * Nn + i + 1) * Nn);
            const float4* s4 = reinterpret_cast<const float4*>(
                smask + ((size_t)b * Nn + i + 1) * Nn);
            for (int u = t - 144; u < 128; u += 112) {
                if (u < 64) reinterpret_cast<float4*>(sm + OFF_ADJ)[u] = a4[u];
                else reinterpret_cast<float4*>(sm + OFF_SM2)[u - 64] = s4[u - 64];
            }
        }
        __syncthreads();

        // ---- Phase D: GRUs for owned 24 columns, bulk-broadcast H ----
        if (t < DSL) {
            const int j = t;
            float rC = 1.f / (1.f + __expf(-(sm[OFF_GI + j] + sm[OFF_GC + j])));
            float zC = 1.f / (1.f + __expf(-(sm[OFF_GI + 24 + j] + sm[OFF_GC + 24 + j])));
            float nC = tanhf(sm[OFF_GI + 48 + j] + rC * sm[OFF_GC + 48 + j]);
            float m = sm[OFF_M + c * DSL + j];
            float Cv = (1.f - zC) * nC + zC * m;
            float rP = 1.f / (1.f + __expf(-(sm[OFF_GP + j] + sm[OFF_GH + j])));
            float zP = 1.f / (1.f + __expf(-(sm[OFF_GP + 24 + j] + sm[OFF_GH + 24 + j])));
            float nP = tanhf(sm[OFF_GP + 48 + j] + rP * sm[OFF_GH + 48 + j]);
            float x = sm[OFF_X + j];
            float Pv = (1.f - zP) * nP + zP * x;
            float h = Cv + Pv;
            sm[OFF_HS + j] = h;           // stage own H slice (96B)
            Hcat[row * HCW + (layer + 1) * DH + c * DSL + j] = h;
        }
        if (warp == 0) {
            __syncwarp();
            if (t == 0) {
                asm volatile("fence.proxy.async.shared::cta;" ::: "memory");
                bulk_bcast_slice(stgH, dstH, mbH);   // ONE 96B bulk per rank
            }
        }
        mbar_wait_parity(mbH, par);   // full H everywhere

        // ---- Phase E: V0/V1 rows (owned cols) + Ksc[i] (replicated) ----
        if (t < 2 * DSL) {
            const int which = t / DSL;
            const int j = t % DSL;
            const float* W = sm + (which ? OFF_WR1 : OFF_WR0);
            float a0 = 0.f, a1 = 0.f, a2 = 0.f, a3 = 0.f;
#pragma unroll 8
            for (int d4 = 0; d4 < 48; ++d4) {
                float4 h4 = sH4[d4];
                const float4 w4 = *reinterpret_cast<const float4*>(W + (d4 * DSL + j) * 4);
                a0 = fmaf(h4.x, w4.x, a0);
                a1 = fmaf(h4.y, w4.y, a1);
                a2 = fmaf(h4.z, w4.z, a2);
                a3 = fmaf(h4.w, w4.w, a3);
            }
            sm[(which ? OFF_V1 : OFF_V0) + i * DSL + j] = (a0 + a1) + (a2 + a3);
        } else if (t >= 64 && t < 96) {
            float s2 = 0.f;
            for (int q = lane; q < DH; q += 32) s2 += sm[OFF_H + q] * sm[OFF_WK + q];
            s2 = warpRedSum(s2);
            if (lane == 0) sm[OFF_KSC + i] = s2;
        }
        __syncthreads();
    }
    cluster_sync_();
}

extern "C" void kernel_launch(void* const* d_in, const int* in_sizes, int n_in,
                              void* d_out, int out_size)
{
    (void)in_sizes; (void)n_in; (void)out_size;
    const float* features = (const float*)d_in[0];
    const float* adj      = (const float*)d_in[1];
    const float* smask    = (const float*)d_in[2];
    const float* fc1_w    = (const float*)d_in[5];
    const float* fc1_b    = (const float*)d_in[6];
    const float* gat_w    = (const float*)d_in[7];
    const float* wr0      = (const float*)d_in[9];
    const float* wr1      = (const float*)d_in[10];
    const float* gruc_wih = (const float*)d_in[11];
    const float* gruc_whh = (const float*)d_in[12];
    const float* gruc_bih = (const float*)d_in[13];
    const float* gruc_bhh = (const float*)d_in[14];
    const float* grup_wih = (const float*)d_in[15];
    const float* grup_whh = (const float*)d_in[16];
    const float* grup_bih = (const float*)d_in[17];
    const float* grup_bhh = (const float*)d_in[18];
    const float* mlp_w0   = (const float*)d_in[19];
    const float* mlp_b0   = (const float*)d_in[20];
    const float* mlp_w1   = (const float*)d_in[21];
    const float* mlp_b1   = (const float*)d_in[22];
    const float* mlp_w2   = (const float*)d_in[23];
    const float* mlp_b2   = (const float*)d_in[24];

    float *pHcat, *pGI, *pGH, *ph1, *ph2;
    cudaGetSymbolAddress((void**)&pHcat, g_Hcat);
    cudaGetSymbolAddress((void**)&pGI, g_GI);
    cudaGetSymbolAddress((void**)&pGH, g_GH);
    cudaGetSymbolAddress((void**)&ph1, g_h1);
    cudaGetSymbolAddress((void**)&ph2, g_h2);

    float* out = (float*)d_out;
    float* out_attn = out + (size_t)Bb * Nn * DCc;

    const int M = Bb * Nn;
    const dim3 blk(256);

    cudaFuncSetAttribute(scan2_kernel, cudaFuncAttributeMaxDynamicSharedMemorySize,
                         SCAN_SMEM_BYTES);

    gemm_kernel<0, 1><<<dim3(DH / 64, M / 64), blk>>>(
        features, fc1_w, fc1_b, pHcat, M, DH, DEe, DEe, 0, HCW, 0);

    for (int l = 0; l < Ll; ++l) {
        gemm_kernel<1, 0><<<dim3(G3 / 64, M / 64), blk>>>(
            pHcat, gruc_wih + (size_t)l * G3 * DH, gruc_bih + l * G3, pGI,
            M, G3, DH, HCW, l * DH, G3, 0);
        gemm_kernel<1, 0><<<dim3(G3 / 64, M / 64), blk>>>(
            pHcat, grup_whh + (size_t)l * G3 * DH, grup_bhh + l * G3, pGH,
            M, G3, DH, HCW, l * DH, G3, 0);

        cudaLaunchConfig_t cfg = {};
        cfg.gridDim = dim3(Bb * CSZ, 1, 1);
        cfg.blockDim = dim3(256, 1, 1);
        cfg.dynamicSmemBytes = SCAN_SMEM_BYTES;
        cudaLaunchAttribute attrs[1];
        attrs[0].id = cudaLaunchAttributeClusterDimension;
        attrs[0].val.clusterDim = {CSZ, 1, 1};
        cfg.attrs = attrs;
        cfg.numAttrs = 1;
        cudaLaunchKernelEx(&cfg, scan2_kernel,
            adj, smask, (const float*)pGI, (const float*)pGH,
            gruc_whh + (size_t)l * G3 * DH,
            grup_wih + (size_t)l * G3 * DH,
            gruc_bhh + l * G3, grup_bih + l * G3,
            wr0 + (size_t)l * DH * DH, wr1 + (size_t)l * DH * DH,
            gat_w + (size_t)l * 2 * DH + DH,
            pHcat, l, out_attn);
    }

    gemm_kernel<0, 1><<<dim3(DH / 64, M / 64), blk>>>(
        pHcat, mlp_w0, mlp_b0, ph1, M, DH, HCW, HCW, 0, DH, 0);
    gemm_kernel<0, 1><<<dim3(DH / 64, M / 64), blk>>>(
        ph1, mlp_w1, mlp_b1, ph2, M, DH, DH, DH, 0, DH, 0);
    gemm_kernel<0, 0><<<dim3(DCc / 64, M / 64), blk>>>(
        ph2, mlp_w2, mlp_b2, out, M, DCc, DH, DH, 0, DCc, 0);
}

// round 11
// speedup vs baseline: 1.3246x; 1.3246x over previous
#include <cuda_runtime.h>
#include <cuda_bf16.h>
#include <cstdint>
#include <math.h>

#define Bb 8
#define Nn 256
#define DEe 768
#define DH 192
#define Ll 2
#define DCc 192
#define G3 576
#define HCW 576
#define CSZ 8           // cluster size (CTAs per batch)
#define DSL 24          // DH / CSZ columns per CTA
#define NTH 288         // threads per scan CTA

// ---- smem float offsets (scan kernel) ----
#define OFF_V0   0        // 6144
#define OFF_V1   6144     // 6144
#define OFF_KSC  12288    // 256
#define OFF_A0   12544    // 256
#define OFF_A1   12800    // 256
#define OFF_ADJ  13056    // 256
#define OFF_SM2  13312    // 256
#define OFF_M    13568    // 192 (16B aligned)
#define OFF_H    13760    // 192 (16B aligned)
#define OFF_G    13952    // 144 gate outputs [ghC(72) | giP(72)]
#define OFF_GI   14096    // 72
#define OFF_GH   14168    // 72
#define OFF_X    14240    // 24
#define OFF_B    14264    // 144 bias
#define OFF_MP   14408    // 288 scratch (B partials / C combine / E partials)
#define OFF_KP   14696    // 8 ksc partials
#define OFF_RED2 14704    // 9
#define OFF_WKP  14713    // 24
#define OFF_MBAR 14744    // 2 x u64 mbarriers (8B aligned: 14744*4=58976)
#define SCAN_SMEM_FLOATS 14748
#define SCAN_SMEM_BYTES (SCAN_SMEM_FLOATS * 4)

__device__ float g_Hcat[Bb * Nn * HCW];
__device__ float g_GI[Bb * Nn * G3];
__device__ float g_GH[Bb * Nn * G3];
__device__ float g_h1[Bb * Nn * DH];
__device__ float g_h2[Bb * Nn * DH];

__device__ __forceinline__ float warpRedSum(float v) {
#pragma unroll
    for (int o = 16; o > 0; o >>= 1) v += __shfl_xor_sync(0xffffffffu, v, o);
    return v;
}
__device__ __forceinline__ void cluster_sync_() {
    asm volatile("barrier.cluster.arrive.aligned;" ::: "memory");
    asm volatile("barrier.cluster.wait.aligned;" ::: "memory");
}
__device__ __forceinline__ uint32_t smem_u32(const void* p) {
    uint32_t a;
    asm("{ .reg .u64 t; cvta.to.shared.u64 t, %1; cvt.u32.u64 %0, t; }" : "=r"(a) : "l"(p));
    return a;
}
// async store of v to the same smem slot in all 8 cluster CTAs,
// accounting 4 bytes on each remote mbarrier.
__device__ __forceinline__ void bcast_async(float* p, uint32_t mbar_loc, float v) {
    uint32_t a = smem_u32(p);
#pragma unroll
    for (int r = 0; r < CSZ; ++r) {
        uint32_t ra, rb;
        asm("mapa.shared::cluster.u32 %0, %1, %2;" : "=r"(ra) : "r"(a), "r"(r));
        asm("mapa.shared::cluster.u32 %0, %1, %2;" : "=r"(rb) : "r"(mbar_loc), "r"(r));
        asm volatile(
            "st.async.shared::cluster.mbarrier::complete_tx::bytes.f32 [%0], %1, [%2];"
            :: "r"(ra), "f"(v), "r"(rb) : "memory");
    }
}
__device__ __forceinline__ void mbar_wait_parity(uint32_t mbar, uint32_t parity) {
    uint32_t done;
    asm volatile(
        "{\n\t.reg .pred p;\n\t"
        "mbarrier.try_wait.parity.acquire.cta.shared::cta.b64 p, [%1], %2;\n\t"
        "selp.b32 %0, 1, 0, p;\n\t}"
        : "=r"(done) : "r"(mbar), "r"(parity) : "memory");
    while (!done) {
        asm volatile(
            "{\n\t.reg .pred p;\n\t"
            "mbarrier.try_wait.parity.acquire.cta.shared::cta.b64 p, [%1], %2, 0x989680;\n\t"
            "selp.b32 %0, 1, 0, p;\n\t}"
            : "=r"(done) : "r"(mbar), "r"(parity) : "memory");
    }
}

// ---------------- generic tiled SGEMM (prologue / epilogue) ----------------
template <int TRANSB, int RELU>
__global__ __launch_bounds__(256) void gemm_kernel(
    const float* __restrict__ A, const float* __restrict__ Bm,
    const float* __restrict__ bias, float* __restrict__ C,
    int M, int Nc, int K, int lda, int aoff, int ldc, int coff)
{
    __shared__ float As[16][65];
    __shared__ float Bs[16][65];
    const int tid = threadIdx.x;
    const int bm = blockIdx.y * 64;
    const int bn = blockIdx.x * 64;
    const int tx = tid & 15;
    const int ty = tid >> 4;
    float acc[4][4] = {};

    for (int k0 = 0; k0 < K; k0 += 16) {
        {
            int r = tid >> 2, cs = (tid & 3) * 4;
            float4 v = *reinterpret_cast<const float4*>(
                A + (size_t)(bm + r) * lda + aoff + k0 + cs);
            As[cs + 0][r] = v.x; As[cs + 1][r] = v.y;
            As[cs + 2][r] = v.z; As[cs + 3][r] = v.w;
        }
        if (TRANSB) {
            int n = tid >> 2, ks = (tid & 3) * 4;
            float4 v = *reinterpret_cast<const float4*>(
                Bm + (size_t)(bn + n) * K + k0 + ks);
            Bs[ks + 0][n] = v.x; Bs[ks + 1][n] = v.y;
            Bs[ks + 2][n] = v.z; Bs[ks + 3][n] = v.w;
        } else {
            int r = tid >> 4, cs = (tid & 15) * 4;
            float4 v = *reinterpret_cast<const float4*>(
                Bm + (size_t)(k0 + r) * Nc + bn + cs);
            Bs[r][cs + 0] = v.x; Bs[r][cs + 1] = v.y;
            Bs[r][cs + 2] = v.z; Bs[r][cs + 3] = v.w;
        }
        __syncthreads();
#pragma unroll
        for (int k = 0; k < 16; ++k) {
            float a[4], bv[4];
#pragma unroll
            for (int q = 0; q < 4; ++q) a[q] = As[k][ty * 4 + q];
#pragma unroll
            for (int q = 0; q < 4; ++q) bv[q] = Bs[k][tx * 4 + q];
#pragma unroll
            for (int p = 0; p < 4; ++p)
#pragma unroll
                for (int q = 0; q < 4; ++q)
                    acc[p][q] = fmaf(a[p], bv[q], acc[p][q]);
        }
        __syncthreads();
    }
#pragma unroll
    for (int p = 0; p < 4; ++p) {
        const int m = bm + ty * 4 + p;
#pragma unroll
        for (int q = 0; q < 4; ++q) {
            const int n = bn + tx * 4 + q;
            float v = acc[p][q] + bias[n];
            if (RELU) v = fmaxf(v, 0.f);
            C[(size_t)m * ldc + coff + n] = v;
        }
    }
}

// ---------------- clustered scan: 8 CTAs/batch, register-resident weights ----
__global__ __launch_bounds__(NTH, 1) void scan2_kernel(
    const float* __restrict__ adj, const float* __restrict__ smask,
    const float* __restrict__ GIc, const float* __restrict__ GHp,
    const float* __restrict__ cwhh,   // (576,192)
    const float* __restrict__ pwih,   // (576,192)
    const float* __restrict__ cbhh, const float* __restrict__ pbih,
    const float* __restrict__ wr0, const float* __restrict__ wr1, // (192,192)
    const float* __restrict__ wk,
    float* __restrict__ Hcat, int layer,
    float* __restrict__ attn_out)
{
    extern __shared__ float sm[];
    const int t = threadIdx.x;
    const int lane = t & 31;
    const int warp = t >> 5;
    uint32_t c;
    asm("mov.u32 %0, %%cluster_ctarank;" : "=r"(c));
    const int b = blockIdx.x / CSZ;

    const uint32_t mbM = smem_u32(sm + OFF_MBAR);
    const uint32_t mbH = mbM + 8;

    // ---- per-thread register weights ----
    // Phase C: output o = t - 144*half (half = t>=144), inputs [half*96, +96)
    //   o<72 -> gh_C row of cwhh ; o>=72 -> gi_P row of pwih
    // Phase E: part = t/48, out oe = t%48 (oe<24 -> V0 col, else V1), inputs [part*32,+32)
    float wreg[96];
    float vreg[32];
    {
        const int half = (t >= 144) ? 1 : 0;
        const int op = t - 144 * half;
        const int o72 = (op < 72) ? op : op - 72;
        const float* Wmat = (op < 72) ? cwhh : pwih;
        const int colg = (o72 / DSL) * DH + c * DSL + (o72 % DSL);
        const float* src = Wmat + (size_t)colg * DH + half * 96;
#pragma unroll
        for (int k4 = 0; k4 < 24; ++k4) {
            float4 v = *reinterpret_cast<const float4*>(src + 4 * k4);
            wreg[k4 * 4 + 0] = v.x; wreg[k4 * 4 + 1] = v.y;
            wreg[k4 * 4 + 2] = v.z; wreg[k4 * 4 + 3] = v.w;
        }
        const int part = t / 48, oe = t % 48;
        const float* We = (oe < DSL) ? wr0 : wr1;
        const float* esrc = We + (size_t)(c * DSL + (oe % DSL)) * DH + part * 32;
#pragma unroll
        for (int k4 = 0; k4 < 8; ++k4) {
            float4 v = *reinterpret_cast<const float4*>(esrc + 4 * k4);
            vreg[k4 * 4 + 0] = v.x; vreg[k4 * 4 + 1] = v.y;
            vreg[k4 * 4 + 2] = v.z; vreg[k4 * 4 + 3] = v.w;
        }
    }
    // ---- prologue smem ----
    if (t < 144) {
        const int o72 = (t < 72) ? t : t - 72;
        const int colg = (o72 / DSL) * DH + c * DSL + (o72 % DSL);
        sm[OFF_B + t] = (t < 72) ? cbhh[colg] : pbih[colg];
    }
    if (t < DSL) sm[OFF_WKP + t] = wk[c * DSL + t];
    if (t < Nn) {
        sm[OFF_KSC + t] = 0.f;
        sm[OFF_ADJ + t] = 0.f;
        sm[OFF_SM2 + t] = 0.f;
    }
    if (t == 0) {
        asm volatile("mbarrier.init.shared.b64 [%0], 1;" :: "r"(mbM) : "memory");
        asm volatile("mbarrier.init.shared.b64 [%0], 1;" :: "r"(mbH) : "memory");
    }
    __syncthreads();
    cluster_sync_();   // mbarriers + smem visible cluster-wide before any st.async

    const int dB = t % DSL;          // Phase-B column
    const int gB = t / DSL;          // Phase-B group (0..11)
    const float4* sM4 = reinterpret_cast<const float4*>(sm + OFF_M);
    const float4* sH4 = reinterpret_cast<const float4*>(sm + OFF_H);

    for (int i = 0; i < Nn; ++i) {
        const size_t row = (size_t)b * Nn + i;
        const uint32_t par = (uint32_t)(i & 1);

        if (t == 0) {
            asm volatile("mbarrier.arrive.expect_tx.shared.b64 _, [%0], %1;"
                         :: "r"(mbM), "r"(768u) : "memory");
            asm volatile("mbarrier.arrive.expect_tx.shared.b64 _, [%0], %1;"
                         :: "r"(mbH), "r"(800u) : "memory");   // 8 x (24 h + 1 ksc) x 4B
        }

        // ---- Phase A: masked softmax (no max-shift; logits bounded) ----
        float e = 0.f, smv = 0.f;
        if (t < Nn) {
            float ksct = sm[OFF_KSC + t];
            if (t == i - 1) {
                float s = sm[OFF_KP + 0] + sm[OFF_KP + 1] + sm[OFF_KP + 2] + sm[OFF_KP + 3]
                        + sm[OFF_KP + 4] + sm[OFF_KP + 5] + sm[OFF_KP + 6] + sm[OFF_KP + 7];
                ksct = s;
                sm[OFF_KSC + t] = s;
            }
            bool valid = (t < i) && (sm[OFF_ADJ + t] > 0.5f);
            smv = sm[OFF_SM2 + t];
            e = valid ? __expf(ksct) : 0.f;
        }
        float ws = warpRedSum(e);
        if (lane == 0) sm[OFF_RED2 + warp] = ws;
        __syncthreads();
        float tot = sm[OFF_RED2 + 0];
#pragma unroll
        for (int q = 1; q < 9; ++q) tot += sm[OFF_RED2 + q];
        if (t < Nn) {
            float attn = 0.f;
            if (i > 0) attn = e / tot;
            float a0 = attn * smv;
            sm[OFF_A0 + t] = a0;
            sm[OFF_A1 + t] = attn - a0;
            if (c == 0)
                attn_out[(((size_t)b * Ll + layer) * Nn + i) * Nn + t] = attn;
        }
        __syncthreads();

        // ---- Phase B: issue gmem prefetches, compute partial M (12 groups) ----
        float pf_s = 0.f;
        float4 pf_v = make_float4(0.f, 0.f, 0.f, 0.f);
        if (t < 72) {
            const int colg = (t / DSL) * DH + c * DSL + (t % DSL);
            pf_s = GIc[row * G3 + colg];
        } else if (t < 144) {
            const int u = t - 72;
            const int colg = (u / DSL) * DH + c * DSL + (u % DSL);
            pf_s = GHp[row * G3 + colg];
        } else if (t < 168) {
            pf_s = Hcat[row * HCW + layer * DH + c * DSL + (t - 144)];
        }
        if (t >= 160 && i + 1 < Nn) {
            const float4* a4 = reinterpret_cast<const float4*>(
                adj + ((size_t)b * Nn + i + 1) * Nn);
            const float4* s4 = reinterpret_cast<const float4*>(
                smask + ((size_t)b * Nn + i + 1) * Nn);
            pf_v = (t < 224) ? a4[t - 160] : s4[t - 224];
        }
        {
            float acc = 0.f;
            for (int n = gB; n < i; n += 12) {
                acc = fmaf(sm[OFF_A0 + n], sm[OFF_V0 + n * DSL + dB], acc);
                acc = fmaf(sm[OFF_A1 + n], sm[OFF_V1 + n * DSL + dB], acc);
            }
            sm[OFF_MP + gB * DSL + dB] = acc;
        }
        if (t < 72) sm[OFF_GI + t] = pf_s;
        else if (t < 144) sm[OFF_GH + (t - 72)] = pf_s;
        else if (t < 168) sm[OFF_X + (t - 144)] = pf_s;
        if (t >= 160 && i + 1 < Nn) {
            if (t < 224) reinterpret_cast<float4*>(sm + OFF_ADJ)[t - 160] = pf_v;
            else reinterpret_cast<float4*>(sm + OFF_SM2)[t - 224] = pf_v;
        }
        __syncthreads();
        if (t < DSL) {
            float v = sm[OFF_MP + t];
#pragma unroll
            for (int g = 1; g < 12; ++g) v += sm[OFF_MP + g * DSL + t];
            bcast_async(sm + OFF_M + c * DSL + t, mbM, v);   // M exchange
        }
        mbar_wait_parity(mbM, par);   // full M everywhere

        // ---- Phase C: gates, 2 threads/output, register weights ----
        float psC;
        {
            const int half = (t >= 144) ? 1 : 0;
            const int o = t - 144 * half;
            const float4* m4 = sM4 + half * 24;
            float a0 = 0.f, a1 = 0.f, a2 = 0.f, a3 = 0.f;
#pragma unroll
            for (int k4 = 0; k4 < 24; ++k4) {
                float4 m = m4[k4];
                a0 = fmaf(m.x, wreg[k4 * 4 + 0], a0);
                a1 = fmaf(m.y, wreg[k4 * 4 + 1], a1);
                a2 = fmaf(m.z, wreg[k4 * 4 + 2], a2);
                a3 = fmaf(m.w, wreg[k4 * 4 + 3], a3);
            }
            psC = (a0 + a1) + (a2 + a3);
            if (half) sm[OFF_MP + o] = psC;
        }
        __syncthreads();
        if (t < 144) sm[OFF_G + t] = psC + sm[OFF_MP + t] + sm[OFF_B + t];
        __syncthreads();

        // ---- Phase D: GRUs (warp 0), H exchange + ksc partial piggyback ----
        if (warp == 0) {
            const int j = lane;
            float h = 0.f, kpart = 0.f;
            if (j < DSL) {
                float rC = 1.f / (1.f + __expf(-(sm[OFF_GI + j] + sm[OFF_G + j])));
                float zC = 1.f / (1.f + __expf(-(sm[OFF_GI + 24 + j] + sm[OFF_G + 24 + j])));
                float nC = tanhf(sm[OFF_GI + 48 + j] + rC * sm[OFF_G + 48 + j]);
                float m = sm[OFF_M + c * DSL + j];
                float Cv = (1.f - zC) * nC + zC * m;
                float rP = 1.f / (1.f + __expf(-(sm[OFF_G + 72 + j] + sm[OFF_GH + j])));
                float zP = 1.f / (1.f + __expf(-(sm[OFF_G + 96 + j] + sm[OFF_GH + 24 + j])));
                float nP = tanhf(sm[OFF_G + 120 + j] + rP * sm[OFF_GH + 48 + j]);
                float x = sm[OFF_X + j];
                float Pv = (1.f - zP) * nP + zP * x;
                h = Cv + Pv;
                Hcat[row * HCW + (layer + 1) * DH + c * DSL + j] = h;
                kpart = h * sm[OFF_WKP + j];
            }
            float ks = warpRedSum(kpart);
            if (j < DSL) bcast_async(sm + OFF_H + c * DSL + j, mbH, h);
            if (j == 0) bcast_async(sm + OFF_KP + c, mbH, ks);
        }
        mbar_wait_parity(mbH, par);   // full H + ksc partials everywhere

        // ---- Phase E: V0/V1 row i, 6 threads/output, register weights ----
        {
            const int part = t / 48, oe = t % 48;
            const float4* h4p = sH4 + part * 8;
            float a0 = 0.f, a1 = 0.f, a2 = 0.f, a3 = 0.f;
#pragma unroll
            for (int k4 = 0; k4 < 8; ++k4) {
                float4 h4 = h4p[k4];
                a0 = fmaf(h4.x, vreg[k4 * 4 + 0], a0);
                a1 = fmaf(h4.y, vreg[k4 * 4 + 1], a1);
                a2 = fmaf(h4.z, vreg[k4 * 4 + 2], a2);
                a3 = fmaf(h4.w, vreg[k4 * 4 + 3], a3);
            }
            float ps = (a0 + a1) + (a2 + a3);
            if (part > 0) sm[OFF_MP + (part - 1) * 48 + oe] = ps;
            __syncthreads();
            if (t < 48) {
                float v = ps;
#pragma unroll
                for (int p = 0; p < 5; ++p) v += sm[OFF_MP + p * 48 + t];
                sm[((t < DSL) ? OFF_V0 : OFF_V1) + i * DSL + (t % DSL)] = v;
            }
        }
        __syncthreads();
    }
    cluster_sync_();
}

extern "C" void kernel_launch(void* const* d_in, const int* in_sizes, int n_in,
                              void* d_out, int out_size)
{
    (void)in_sizes; (void)n_in; (void)out_size;
    const float* features = (const float*)d_in[0];
    const float* adj      = (const float*)d_in[1];
    const float* smask    = (const float*)d_in[2];
    const float* fc1_w    = (const float*)d_in[5];
    const float* fc1_b    = (const float*)d_in[6];
    const float* gat_w    = (const float*)d_in[7];
    const float* wr0      = (const float*)d_in[9];
    const float* wr1      = (const float*)d_in[10];
    const float* gruc_wih = (const float*)d_in[11];
    const float* gruc_whh = (const float*)d_in[12];
    const float* gruc_bih = (const float*)d_in[13];
    const float* gruc_bhh = (const float*)d_in[14];
    const float* grup_wih = (const float*)d_in[15];
    const float* grup_whh = (const float*)d_in[16];
    const float* grup_bih = (const float*)d_in[17];
    const float* grup_bhh = (const float*)d_in[18];
    const float* mlp_w0   = (const float*)d_in[19];
    const float* mlp_b0   = (const float*)d_in[20];
    const float* mlp_w1   = (const float*)d_in[21];
    const float* mlp_b1   = (const float*)d_in[22];
    const float* mlp_w2   = (const float*)d_in[23];
    const float* mlp_b2   = (const float*)d_in[24];

    float *pHcat, *pGI, *pGH, *ph1, *ph2;
    cudaGetSymbolAddress((void**)&pHcat, g_Hcat);
    cudaGetSymbolAddress((void**)&pGI, g_GI);
    cudaGetSymbolAddress((void**)&pGH, g_GH);
    cudaGetSymbolAddress((void**)&ph1, g_h1);
    cudaGetSymbolAddress((void**)&ph2, g_h2);

    float* out = (float*)d_out;
    float* out_attn = out + (size_t)Bb * Nn * DCc;

    const int M = Bb * Nn;
    const dim3 blk(256);

    cudaFuncSetAttribute(scan2_kernel, cudaFuncAttributeMaxDynamicSharedMemorySize,
                         SCAN_SMEM_BYTES);

    gemm_kernel<0, 1><<<dim3(DH / 64, M / 64), blk>>>(
        features, fc1_w, fc1_b, pHcat, M, DH, DEe, DEe, 0, HCW, 0);

    for (int l = 0; l < Ll; ++l) {
        gemm_kernel<1, 0><<<dim3(G3 / 64, M / 64), blk>>>(
            pHcat, gruc_wih + (size_t)l * G3 * DH, gruc_bih + l * G3, pGI,
            M, G3, DH, HCW, l * DH, G3, 0);
        gemm_kernel<1, 0><<<dim3(G3 / 64, M / 64), blk>>>(
            pHcat, grup_whh + (size_t)l * G3 * DH, grup_bhh + l * G3, pGH,
            M, G3, DH, HCW, l * DH, G3, 0);

        cudaLaunchConfig_t cfg = {};
        cfg.gridDim = dim3(Bb * CSZ, 1, 1);
        cfg.blockDim = dim3(NTH, 1, 1);
        cfg.dynamicSmemBytes = SCAN_SMEM_BYTES;
        cudaLaunchAttribute attrs[1];
        attrs[0].id = cudaLaunchAttributeClusterDimension;
        attrs[0].val.clusterDim = {CSZ, 1, 1};
        cfg.attrs = attrs;
        cfg.numAttrs = 1;
        cudaLaunchKernelEx(&cfg, scan2_kernel,
            adj, smask, (const float*)pGI, (const float*)pGH,
            gruc_whh + (size_t)l * G3 * DH,
            grup_wih + (size_t)l * G3 * DH,
            gruc_bhh + l * G3, grup_bih + l * G3,
            wr0 + (size_t)l * DH * DH, wr1 + (size_t)l * DH * DH,
            gat_w + (size_t)l * 2 * DH + DH,
            pHcat, l, out_attn);
    }

    gemm_kernel<0, 1><<<dim3(DH / 64, M / 64), blk>>>(
        pHcat, mlp_w0, mlp_b0, ph1, M, DH, HCW, HCW, 0, DH, 0);
    gemm_kernel<0, 1><<<dim3(DH / 64, M / 64), blk>>>(
        ph1, mlp_w1, mlp_b1, ph2, M, DH, DH, DH, 0, DH, 0);
    gemm_kernel<0, 0><<<dim3(DCc / 64, M / 64), blk>>>(
        ph2, mlp_w2, mlp_b2, out, M, DCc, DH, DH, 0, DCc, 0);
}

// round 12
// speedup vs baseline: 1.3255x; 1.0007x over previous
#include <cuda_runtime.h>
#include <cuda_bf16.h>
#include <cstdint>
#include <math.h>

#define Bb 8
#define Nn 256
#define DEe 768
#define DH 192
#define Ll 2
#define DCc 192
#define G3 576
#define HCW 576
#define CSZ 8           // cluster size (CTAs per batch)
#define DSL 24          // DH / CSZ columns per CTA
#define NTH 288         // threads per scan CTA

// ---- smem float offsets (scan kernel) ----
#define OFF_V0   0        // 6144
#define OFF_V1   6144     // 6144
#define OFF_KSC  12288    // 256
#define OFF_A0   12544    // 256
#define OFF_A1   12800    // 256
#define OFF_ADJ  13056    // 256
#define OFF_SM2  13312    // 256
#define OFF_M    13568    // 192 (16B aligned)
#define OFF_H    13760    // 192 (16B aligned)
#define OFF_G    13952    // 144 gate outputs [ghC(72) | giP(72)]
#define OFF_GI   14096    // 72
#define OFF_GH   14168    // 72
#define OFF_X    14240    // 24
#define OFF_B    14264    // 144 bias
#define OFF_MP   14408    // 288 scratch (B partials / C combine / E partials)
#define OFF_KP   14696    // 8 ksc partials
#define OFF_RED2 14704    // 9
#define OFF_WKP  14713    // 24
#define OFF_MBAR 14744    // 2 x u64 mbarriers (8B aligned: 14744*4=58976)
#define SCAN_SMEM_FLOATS 14748
#define SCAN_SMEM_BYTES (SCAN_SMEM_FLOATS * 4)

__device__ float g_Hcat[Bb * Nn * HCW];
__device__ float g_GI[Bb * Nn * G3];
__device__ float g_GH[Bb * Nn * G3];
__device__ float g_h1[Bb * Nn * DH];
__device__ float g_h2[Bb * Nn * DH];

typedef unsigned long long ull;

__device__ __forceinline__ float warpRedSum(float v) {
#pragma unroll
    for (int o = 16; o > 0; o >>= 1) v += __shfl_xor_sync(0xffffffffu, v, o);
    return v;
}
__device__ __forceinline__ void cluster_sync_() {
    asm volatile("barrier.cluster.arrive.aligned;" ::: "memory");
    asm volatile("barrier.cluster.wait.aligned;" ::: "memory");
}
__device__ __forceinline__ uint32_t smem_u32(const void* p) {
    uint32_t a;
    asm("{ .reg .u64 t; cvta.to.shared.u64 t, %1; cvt.u32.u64 %0, t; }" : "=r"(a) : "l"(p));
    return a;
}
__device__ __forceinline__ ull fma2_(ull a, ull b, ull c) {
    ull d;
    asm("fma.rn.f32x2 %0, %1, %2, %3;" : "=l"(d) : "l"(a), "l"(b), "l"(c));
    return d;
}
__device__ __forceinline__ float sum2_(ull v) {
    float lo, hi;
    asm("mov.b64 {%0, %1}, %2;" : "=f"(lo), "=f"(hi) : "l"(v));
    return lo + hi;
}
// async store of v to the same smem slot in all 8 cluster CTAs,
// accounting 4 bytes on each remote mbarrier.
__device__ __forceinline__ void bcast_async(float* p, uint32_t mbar_loc, float v) {
    uint32_t a = smem_u32(p);
#pragma unroll
    for (int r = 0; r < CSZ; ++r) {
        uint32_t ra, rb;
        asm("mapa.shared::cluster.u32 %0, %1, %2;" : "=r"(ra) : "r"(a), "r"(r));
        asm("mapa.shared::cluster.u32 %0, %1, %2;" : "=r"(rb) : "r"(mbar_loc), "r"(r));
        asm volatile(
            "st.async.shared::cluster.mbarrier::complete_tx::bytes.f32 [%0], %1, [%2];"
            :: "r"(ra), "f"(v), "r"(rb) : "memory");
    }
}
__device__ __forceinline__ void mbar_wait_parity(uint32_t mbar, uint32_t parity) {
    uint32_t done;
    asm volatile(
        "{\n\t.reg .pred p;\n\t"
        "mbarrier.try_wait.parity.acquire.cta.shared::cta.b64 p, [%1], %2;\n\t"
        "selp.b32 %0, 1, 0, p;\n\t}"
        : "=r"(done) : "r"(mbar), "r"(parity) : "memory");
    while (!done) {
        asm volatile(
            "{\n\t.reg .pred p;\n\t"
            "mbarrier.try_wait.parity.acquire.cta.shared::cta.b64 p, [%1], %2, 0x989680;\n\t"
            "selp.b32 %0, 1, 0, p;\n\t}"
            : "=r"(done) : "r"(mbar), "r"(parity) : "memory");
    }
}

// ---------------- generic tiled SGEMM (prologue / epilogue) ----------------
template <int TRANSB, int RELU>
__global__ __launch_bounds__(256) void gemm_kernel(
    const float* __restrict__ A, const float* __restrict__ Bm,
    const float* __restrict__ bias, float* __restrict__ C,
    int M, int Nc, int K, int lda, int aoff, int ldc, int coff)
{
    __shared__ float As[16][65];
    __shared__ float Bs[16][65];
    const int tid = threadIdx.x;
    const int bm = blockIdx.y * 64;
    const int bn = blockIdx.x * 64;
    const int tx = tid & 15;
    const int ty = tid >> 4;
    float acc[4][4] = {};

    for (int k0 = 0; k0 < K; k0 += 16) {
        {
            int r = tid >> 2, cs = (tid & 3) * 4;
            float4 v = *reinterpret_cast<const float4*>(
                A + (size_t)(bm + r) * lda + aoff + k0 + cs);
            As[cs + 0][r] = v.x; As[cs + 1][r] = v.y;
            As[cs + 2][r] = v.z; As[cs + 3][r] = v.w;
        }
        if (TRANSB) {
            int n = tid >> 2, ks = (tid & 3) * 4;
            float4 v = *reinterpret_cast<const float4*>(
                Bm + (size_t)(bn + n) * K + k0 + ks);
            Bs[ks + 0][n] = v.x; Bs[ks + 1][n] = v.y;
            Bs[ks + 2][n] = v.z; Bs[ks + 3][n] = v.w;
        } else {
            int r = tid >> 4, cs = (tid & 15) * 4;
            float4 v = *reinterpret_cast<const float4*>(
                Bm + (size_t)(k0 + r) * Nc + bn + cs);
            Bs[r][cs + 0] = v.x; Bs[r][cs + 1] = v.y;
            Bs[r][cs + 2] = v.z; Bs[r][cs + 3] = v.w;
        }
        __syncthreads();
#pragma unroll
        for (int k = 0; k < 16; ++k) {
            float a[4], bv[4];
#pragma unroll
            for (int q = 0; q < 4; ++q) a[q] = As[k][ty * 4 + q];
#pragma unroll
            for (int q = 0; q < 4; ++q) bv[q] = Bs[k][tx * 4 + q];
#pragma unroll
            for (int p = 0; p < 4; ++p)
#pragma unroll
                for (int q = 0; q < 4; ++q)
                    acc[p][q] = fmaf(a[p], bv[q], acc[p][q]);
        }
        __syncthreads();
    }
#pragma unroll
    for (int p = 0; p < 4; ++p) {
        const int m = bm + ty * 4 + p;
#pragma unroll
        for (int q = 0; q < 4; ++q) {
            const int n = bn + tx * 4 + q;
            float v = acc[p][q] + bias[n];
            if (RELU) v = fmaxf(v, 0.f);
            C[(size_t)m * ldc + coff + n] = v;
        }
    }
}

// ---------------- clustered scan: 8 CTAs/batch, packed-f32x2 reg weights ----
__global__ __launch_bounds__(NTH, 1) void scan2_kernel(
    const float* __restrict__ adj, const float* __restrict__ smask,
    const float* __restrict__ GIc, const float* __restrict__ GHp,
    const float* __restrict__ cwhh,   // (576,192)
    const float* __restrict__ pwih,   // (576,192)
    const float* __restrict__ cbhh, const float* __restrict__ pbih,
    const float* __restrict__ wr0, const float* __restrict__ wr1, // (192,192)
    const float* __restrict__ wk,
    float* __restrict__ Hcat, int layer,
    float* __restrict__ attn_out)
{
    extern __shared__ float sm[];
    const int t = threadIdx.x;
    const int lane = t & 31;
    const int warp = t >> 5;
    uint32_t c;
    asm("mov.u32 %0, %%cluster_ctarank;" : "=r"(c));
    const int b = blockIdx.x / CSZ;

    const uint32_t mbM = smem_u32(sm + OFF_MBAR);
    const uint32_t mbH = mbM + 8;

    // ---- per-thread packed register weights ----
    // Phase C: output o = t - 144*half (half = t>=144), inputs [half*96, +96)
    // Phase E: part = t/48, out oe = t%48 (oe<24 -> V0 col, else V1), inputs [part*32,+32)
    ull wp[48];
    ull vp[16];
    {
        const int half = (t >= 144) ? 1 : 0;
        const int op = t - 144 * half;
        const int o72 = (op < 72) ? op : op - 72;
        const float* Wmat = (op < 72) ? cwhh : pwih;
        const int colg = (o72 / DSL) * DH + c * DSL + (o72 % DSL);
        const ulonglong2* src = reinterpret_cast<const ulonglong2*>(
            Wmat + (size_t)colg * DH + half * 96);
#pragma unroll
        for (int k2 = 0; k2 < 24; ++k2) {
            ulonglong2 v = src[k2];
            wp[2 * k2 + 0] = v.x;
            wp[2 * k2 + 1] = v.y;
        }
        const int part = t / 48, oe = t % 48;
        const float* We = (oe < DSL) ? wr0 : wr1;
        const ulonglong2* esrc = reinterpret_cast<const ulonglong2*>(
            We + (size_t)(c * DSL + (oe % DSL)) * DH + part * 32);
#pragma unroll
        for (int k2 = 0; k2 < 8; ++k2) {
            ulonglong2 v = esrc[k2];
            vp[2 * k2 + 0] = v.x;
            vp[2 * k2 + 1] = v.y;
        }
    }
    // ---- prologue smem ----
    if (t < 144) {
        const int o72 = (t < 72) ? t : t - 72;
        const int colg = (o72 / DSL) * DH + c * DSL + (o72 % DSL);
        sm[OFF_B + t] = (t < 72) ? cbhh[colg] : pbih[colg];
    }
    if (t < DSL) sm[OFF_WKP + t] = wk[c * DSL + t];
    if (t < Nn) {
        sm[OFF_KSC + t] = 0.f;
        sm[OFF_ADJ + t] = 0.f;
        sm[OFF_SM2 + t] = 0.f;
    }
    if (t == 0) {
        asm volatile("mbarrier.init.shared.b64 [%0], 1;" :: "r"(mbM) : "memory");
        asm volatile("mbarrier.init.shared.b64 [%0], 1;" :: "r"(mbH) : "memory");
    }
    __syncthreads();
    cluster_sync_();   // mbarriers + smem visible cluster-wide before any st.async

    const int dB = t % DSL;          // Phase-B column
    const int gB = t / DSL;          // Phase-B group (0..11)

    for (int i = 0; i < Nn; ++i) {
        const size_t row = (size_t)b * Nn + i;
        const uint32_t par = (uint32_t)(i & 1);

        if (t == 0) {
            asm volatile("mbarrier.arrive.expect_tx.shared.b64 _, [%0], %1;"
                         :: "r"(mbM), "r"(768u) : "memory");
            asm volatile("mbarrier.arrive.expect_tx.shared.b64 _, [%0], %1;"
                         :: "r"(mbH), "r"(800u) : "memory");   // 8 x (24 h + 1 ksc) x 4B
        }

        // ---- Phase A: masked softmax (no max-shift; logits bounded) ----
        float e = 0.f, smv = 0.f;
        if (t < Nn) {
            float ksct = sm[OFF_KSC + t];
            if (t == i - 1) {
                float s = sm[OFF_KP + 0] + sm[OFF_KP + 1] + sm[OFF_KP + 2] + sm[OFF_KP + 3]
                        + sm[OFF_KP + 4] + sm[OFF_KP + 5] + sm[OFF_KP + 6] + sm[OFF_KP + 7];
                ksct = s;
                sm[OFF_KSC + t] = s;
            }
            bool valid = (t < i) && (sm[OFF_ADJ + t] > 0.5f);
            smv = sm[OFF_SM2 + t];
            e = valid ? __expf(ksct) : 0.f;
        }
        float ws = warpRedSum(e);
        if (lane == 0) sm[OFF_RED2 + warp] = ws;
        __syncthreads();
        float tot = sm[OFF_RED2 + 0];
#pragma unroll
        for (int q = 1; q < 9; ++q) tot += sm[OFF_RED2 + q];
        if (t < Nn) {
            float attn = 0.f;
            if (i > 0) attn = __fdividef(e, tot);
            float a0 = attn * smv;
            sm[OFF_A0 + t] = a0;
            sm[OFF_A1 + t] = attn - a0;
            if (c == 0)
                attn_out[(((size_t)b * Ll + layer) * Nn + i) * Nn + t] = attn;
        }
        __syncthreads();

        // ---- Phase B: issue gmem prefetches, compute partial M (12 groups) ----
        float pf_s = 0.f;
        float4 pf_v = make_float4(0.f, 0.f, 0.f, 0.f);
        if (t < 72) {
            const int colg = (t / DSL) * DH + c * DSL + (t % DSL);
            pf_s = GIc[row * G3 + colg];
        } else if (t < 144) {
            const int u = t - 72;
            const int colg = (u / DSL) * DH + c * DSL + (u % DSL);
            pf_s = GHp[row * G3 + colg];
        } else if (t < 168) {
            pf_s = Hcat[row * HCW + layer * DH + c * DSL + (t - 144)];
        }
        if (t >= 160 && i + 1 < Nn) {
            const float4* a4 = reinterpret_cast<const float4*>(
                adj + ((size_t)b * Nn + i + 1) * Nn);
            const float4* s4 = reinterpret_cast<const float4*>(
                smask + ((size_t)b * Nn + i + 1) * Nn);
            pf_v = (t < 224) ? a4[t - 160] : s4[t - 224];
        }
        {
            float acc0 = 0.f, acc1 = 0.f;
            for (int n = gB; n < i; n += 12) {
                acc0 = fmaf(sm[OFF_A0 + n], sm[OFF_V0 + n * DSL + dB], acc0);
                acc1 = fmaf(sm[OFF_A1 + n], sm[OFF_V1 + n * DSL + dB], acc1);
            }
            sm[OFF_MP + gB * DSL + dB] = acc0 + acc1;
        }
        if (t < 72) sm[OFF_GI + t] = pf_s;
        else if (t < 144) sm[OFF_GH + (t - 72)] = pf_s;
        else if (t < 168) sm[OFF_X + (t - 144)] = pf_s;
        if (t >= 160 && i + 1 < Nn) {
            if (t < 224) reinterpret_cast<float4*>(sm + OFF_ADJ)[t - 160] = pf_v;
            else reinterpret_cast<float4*>(sm + OFF_SM2)[t - 224] = pf_v;
        }
        __syncthreads();
        if (t < DSL) {
            float v = sm[OFF_MP + t];
#pragma unroll
            for (int g = 1; g < 12; ++g) v += sm[OFF_MP + g * DSL + t];
            bcast_async(sm + OFF_M + c * DSL + t, mbM, v);   // M exchange
        }
        mbar_wait_parity(mbM, par);   // full M everywhere

        // ---- Phase C: gates, 2 threads/output, packed f32x2 ----
        float psC;
        {
            const int half = (t >= 144) ? 1 : 0;
            const int o = t - 144 * half;
            const ulonglong2* mm2 = reinterpret_cast<const ulonglong2*>(sm + OFF_M)
                                    + half * 24;
            ull q0 = 0ull, q1 = 0ull, q2 = 0ull, q3 = 0ull;
#pragma unroll
            for (int k2 = 0; k2 < 24; k2 += 2) {
                ulonglong2 m0 = mm2[k2];
                ulonglong2 m1 = mm2[k2 + 1];
                q0 = fma2_(m0.x, wp[2 * k2 + 0], q0);
                q1 = fma2_(m0.y, wp[2 * k2 + 1], q1);
                q2 = fma2_(m1.x, wp[2 * k2 + 2], q2);
                q3 = fma2_(m1.y, wp[2 * k2 + 3], q3);
            }
            psC = (sum2_(q0) + sum2_(q1)) + (sum2_(q2) + sum2_(q3));
            if (half) sm[OFF_MP + o] = psC;
        }
        __syncthreads();
        if (t < 144) sm[OFF_G + t] = psC + sm[OFF_MP + t] + sm[OFF_B + t];
        __syncthreads();

        // ---- Phase D: GRUs (warp 0), H exchange + ksc partial piggyback ----
        if (warp == 0) {
            const int j = lane;
            float h = 0.f, kpart = 0.f;
            if (j < DSL) {
                float rC = 1.f / (1.f + __expf(-(sm[OFF_GI + j] + sm[OFF_G + j])));
                float zC = 1.f / (1.f + __expf(-(sm[OFF_GI + 24 + j] + sm[OFF_G + 24 + j])));
                float nC = tanhf(sm[OFF_GI + 48 + j] + rC * sm[OFF_G + 48 + j]);
                float m = sm[OFF_M + c * DSL + j];
                float Cv = (1.f - zC) * nC + zC * m;
                float rP = 1.f / (1.f + __expf(-(sm[OFF_G + 72 + j] + sm[OFF_GH + j])));
                float zP = 1.f / (1.f + __expf(-(sm[OFF_G + 96 + j] + sm[OFF_GH + 24 + j])));
                float nP = tanhf(sm[OFF_G + 120 + j] + rP * sm[OFF_GH + 48 + j]);
                float x = sm[OFF_X + j];
                float Pv = (1.f - zP) * nP + zP * x;
                h = Cv + Pv;
                Hcat[row * HCW + (layer + 1) * DH + c * DSL + j] = h;
                kpart = h * sm[OFF_WKP + j];
            }
            float ks = warpRedSum(kpart);
            if (j < DSL) bcast_async(sm + OFF_H + c * DSL + j, mbH, h);
            if (j == 0) bcast_async(sm + OFF_KP + c, mbH, ks);
        }
        mbar_wait_parity(mbH, par);   // full H + ksc partials everywhere

        // ---- Phase E: V0/V1 row i, 6 threads/output, packed f32x2 ----
        {
            const int part = t / 48, oe = t % 48;
            const ulonglong2* hh2 = reinterpret_cast<const ulonglong2*>(sm + OFF_H)
                                    + part * 8;
            ull q0 = 0ull, q1 = 0ull, q2 = 0ull, q3 = 0ull;
#pragma unroll
            for (int k2 = 0; k2 < 8; k2 += 2) {
                ulonglong2 h0 = hh2[k2];
                ulonglong2 h1 = hh2[k2 + 1];
                q0 = fma2_(h0.x, vp[2 * k2 + 0], q0);
                q1 = fma2_(h0.y, vp[2 * k2 + 1], q1);
                q2 = fma2_(h1.x, vp[2 * k2 + 2], q2);
                q3 = fma2_(h1.y, vp[2 * k2 + 3], q3);
            }
            float ps = (sum2_(q0) + sum2_(q1)) + (sum2_(q2) + sum2_(q3));
            if (part > 0) sm[OFF_MP + (part - 1) * 48 + oe] = ps;
            __syncthreads();
            if (t < 48) {
                float v = ps;
#pragma unroll
                for (int p = 0; p < 5; ++p) v += sm[OFF_MP + p * 48 + t];
                sm[((t < DSL) ? OFF_V0 : OFF_V1) + i * DSL + (t % DSL)] = v;
            }
        }
        __syncthreads();
    }
    cluster_sync_();
}

extern "C" void kernel_launch(void* const* d_in, const int* in_sizes, int n_in,
                              void* d_out, int out_size)
{
    (void)in_sizes; (void)n_in; (void)out_size;
    const float* features = (const float*)d_in[0];
    const float* adj      = (const float*)d_in[1];
    const float* smask    = (const float*)d_in[2];
    const float* fc1_w    = (const float*)d_in[5];
    const float* fc1_b    = (const float*)d_in[6];
    const float* gat_w    = (const float*)d_in[7];
    const float* wr0      = (const float*)d_in[9];
    const float* wr1      = (const float*)d_in[10];
    const float* gruc_wih = (const float*)d_in[11];
    const float* gruc_whh = (const float*)d_in[12];
    const float* gruc_bih = (const float*)d_in[13];
    const float* gruc_bhh = (const float*)d_in[14];
    const float* grup_wih = (const float*)d_in[15];
    const float* grup_whh = (const float*)d_in[16];
    const float* grup_bih = (const float*)d_in[17];
    const float* grup_bhh = (const float*)d_in[18];
    const float* mlp_w0   = (const float*)d_in[19];
    const float* mlp_b0   = (const float*)d_in[20];
    const float* mlp_w1   = (const float*)d_in[21];
    const float* mlp_b1   = (const float*)d_in[22];
    const float* mlp_w2   = (const float*)d_in[23];
    const float* mlp_b2   = (const float*)d_in[24];

    float *pHcat, *pGI, *pGH, *ph1, *ph2;
    cudaGetSymbolAddress((void**)&pHcat, g_Hcat);
    cudaGetSymbolAddress((void**)&pGI, g_GI);
    cudaGetSymbolAddress((void**)&pGH, g_GH);
    cudaGetSymbolAddress((void**)&ph1, g_h1);
    cudaGetSymbolAddress((void**)&ph2, g_h2);

    float* out = (float*)d_out;
    float* out_attn = out + (size_t)Bb * Nn * DCc;

    const int M = Bb * Nn;
    const dim3 blk(256);

    cudaFuncSetAttribute(scan2_kernel, cudaFuncAttributeMaxDynamicSharedMemorySize,
                         SCAN_SMEM_BYTES);

    gemm_kernel<0, 1><<<dim3(DH / 64, M / 64), blk>>>(
        features, fc1_w, fc1_b, pHcat, M, DH, DEe, DEe, 0, HCW, 0);

    for (int l = 0; l < Ll; ++l) {
        gemm_kernel<1, 0><<<dim3(G3 / 64, M / 64), blk>>>(
            pHcat, gruc_wih + (size_t)l * G3 * DH, gruc_bih + l * G3, pGI,
            M, G3, DH, HCW, l * DH, G3, 0);
        gemm_kernel<1, 0><<<dim3(G3 / 64, M / 64), blk>>>(
            pHcat, grup_whh + (size_t)l * G3 * DH, grup_bhh + l * G3, pGH,
            M, G3, DH, HCW, l * DH, G3, 0);

        cudaLaunchConfig_t cfg = {};
        cfg.gridDim = dim3(Bb * CSZ, 1, 1);
        cfg.blockDim = dim3(NTH, 1, 1);
        cfg.dynamicSmemBytes = SCAN_SMEM_BYTES;
        cudaLaunchAttribute attrs[1];
        attrs[0].id = cudaLaunchAttributeClusterDimension;
        attrs[0].val.clusterDim = {CSZ, 1, 1};
        cfg.attrs = attrs;
        cfg.numAttrs = 1;
        cudaLaunchKernelEx(&cfg, scan2_kernel,
            adj, smask, (const float*)pGI, (const float*)pGH,
            gruc_whh + (size_t)l * G3 * DH,
            grup_wih + (size_t)l * G3 * DH,
            gruc_bhh + l * G3, grup_bih + l * G3,
            wr0 + (size_t)l * DH * DH, wr1 + (size_t)l * DH * DH,
            gat_w + (size_t)l * 2 * DH + DH,
            pHcat, l, out_attn);
    }

    gemm_kernel<0, 1><<<dim3(DH / 64, M / 64), blk>>>(
        pHcat, mlp_w0, mlp_b0, ph1, M, DH, HCW, HCW, 0, DH, 0);
    gemm_kernel<0, 1><<<dim3(DH / 64, M / 64), blk>>>(
        ph1, mlp_w1, mlp_b1, ph2, M, DH, DH, DH, 0, DH, 0);
    gemm_kernel<0, 0><<<dim3(DCc / 64, M / 64), blk>>>(
        ph2, mlp_w2, mlp_b2, out, M, DCc, DH, DH, 0, DCc, 0);
}